// round 1
// baseline (speedup 1.0000x reference)
#include <cuda_runtime.h>
#include <cuda_bf16.h>

// Problem constants (verified against reference: N=50000, E=850000, F=256)
#define NMAX 50000
#define EMAX 850000
#define F 256
#define ALPHA 0.2f

// Scratch (allocation-free rule: __device__ globals)
__device__ float g_h[NMAX * F];       // h = x @ W
__device__ float g_e[EMAX];           // per-edge attention weight
__device__ float g_rowsum[NMAX];      // sum of e per src
__device__ float g_s[NMAX];           // h @ a[:F]
__device__ float g_t[NMAX];           // h @ a[F:]

// ---------------------------------------------------------------------------
// GEMM: h = x @ W   (x: [N,256] row-major, W: [256,256] row-major)
// 64x64 block tile, 32 K-slice, 4x4 per-thread tile, 256 threads.
// ---------------------------------------------------------------------------
#define BM 64
#define BN 64
#define BK 32

__global__ void gemm_kernel(const float* __restrict__ A,
                            const float* __restrict__ B,
                            int M) {
    __shared__ float As[BK][BM];   // transposed A tile
    __shared__ float Bs[BK][BN];

    const int bm = blockIdx.y * BM;
    const int bn = blockIdx.x * BN;
    const int tid = threadIdx.x;
    const int tx = tid & 15;       // 16 thread-cols
    const int ty = tid >> 4;       // 16 thread-rows

    float acc[4][4] = {};

    for (int k0 = 0; k0 < F; k0 += BK) {
        // Load A tile: 64 rows x 32 cols = 512 float4, 2 per thread
        #pragma unroll
        for (int i = 0; i < 2; i++) {
            int idx = tid + i * 256;          // 0..511
            int row = idx >> 3;               // 8 float4 per row
            int kc4 = idx & 7;
            float4 v = make_float4(0.f, 0.f, 0.f, 0.f);
            if (bm + row < M)
                v = *reinterpret_cast<const float4*>(&A[(size_t)(bm + row) * F + k0 + kc4 * 4]);
            As[kc4 * 4 + 0][row] = v.x;
            As[kc4 * 4 + 1][row] = v.y;
            As[kc4 * 4 + 2][row] = v.z;
            As[kc4 * 4 + 3][row] = v.w;
        }
        // Load B tile: 32 rows x 64 cols = 512 float4, 2 per thread
        #pragma unroll
        for (int i = 0; i < 2; i++) {
            int idx = tid + i * 256;
            int kr  = idx >> 4;               // 16 float4 per row
            int nc4 = idx & 15;
            float4 v = *reinterpret_cast<const float4*>(&B[(size_t)(k0 + kr) * F + bn + nc4 * 4]);
            reinterpret_cast<float4*>(&Bs[kr][0])[nc4] = v;
        }
        __syncthreads();

        #pragma unroll
        for (int k = 0; k < BK; k++) {
            float4 a4 = *reinterpret_cast<float4*>(&As[k][ty * 4]);
            float4 b4 = reinterpret_cast<float4*>(&Bs[k][0])[tx];
            float av[4] = {a4.x, a4.y, a4.z, a4.w};
            float bv[4] = {b4.x, b4.y, b4.z, b4.w};
            #pragma unroll
            for (int i = 0; i < 4; i++)
                #pragma unroll
                for (int j = 0; j < 4; j++)
                    acc[i][j] += av[i] * bv[j];
        }
        __syncthreads();
    }

    #pragma unroll
    for (int i = 0; i < 4; i++) {
        int row = bm + ty * 4 + i;
        if (row < M) {
            float4 v = make_float4(acc[i][0], acc[i][1], acc[i][2], acc[i][3]);
            *reinterpret_cast<float4*>(&g_h[(size_t)row * F + bn + tx * 4]) = v;
        }
    }
}

// ---------------------------------------------------------------------------
// s[i] = h[i] . a[:F],  t[i] = h[i] . a[F:]   — one warp per node
// ---------------------------------------------------------------------------
__global__ void st_kernel(const float* __restrict__ a, int N) {
    int node = blockIdx.x * (blockDim.x >> 5) + (threadIdx.x >> 5);
    int lane = threadIdx.x & 31;
    if (node >= N) return;
    float ss = 0.f, tt = 0.f;
    const float* hrow = &g_h[(size_t)node * F];
    #pragma unroll
    for (int f = lane * 4; f < F; f += 32 * 4) {
        float4 hv = *reinterpret_cast<const float4*>(&hrow[f]);
        float4 a1 = *reinterpret_cast<const float4*>(&a[f]);
        float4 a2 = *reinterpret_cast<const float4*>(&a[F + f]);
        ss += hv.x * a1.x + hv.y * a1.y + hv.z * a1.z + hv.w * a1.w;
        tt += hv.x * a2.x + hv.y * a2.y + hv.z * a2.z + hv.w * a2.w;
    }
    #pragma unroll
    for (int off = 16; off > 0; off >>= 1) {
        ss += __shfl_down_sync(0xFFFFFFFF, ss, off);
        tt += __shfl_down_sync(0xFFFFFFFF, tt, off);
    }
    if (lane == 0) {
        g_s[node] = ss;
        g_t[node] = tt;
    }
}

// ---------------------------------------------------------------------------
// Per edge: e = exp(-leaky_relu(s[src]+t[dst])); rowsum[src] += e
// ---------------------------------------------------------------------------
__global__ void edge_kernel(const int* __restrict__ edge, int E) {
    int i = blockIdx.x * blockDim.x + threadIdx.x;
    if (i >= E) return;
    int src = edge[i];
    int dst = edge[E + i];
    float logit = g_s[src] + g_t[dst];
    float l = logit > 0.f ? logit : ALPHA * logit;
    float ev = expf(-l);
    g_e[i] = ev;
    atomicAdd(&g_rowsum[src], ev);
}

// ---------------------------------------------------------------------------
// Message pass: out[src] += e * h[dst].  64 threads per edge (float4 each),
// 4 edges per 256-thread block. red.global.add.v4.f32 (sm_90+) for the scatter.
// ---------------------------------------------------------------------------
__global__ void msg_kernel(const int* __restrict__ edge, float* __restrict__ out, int E) {
    int eidx = blockIdx.x * 4 + (threadIdx.x >> 6);
    int f4 = threadIdx.x & 63;                 // float4 index within row
    if (eidx >= E) return;
    int src = edge[eidx];
    int dst = edge[E + eidx];
    float ev = g_e[eidx];
    float4 hv = reinterpret_cast<const float4*>(&g_h[(size_t)dst * F])[f4];
    float* p = out + (size_t)src * F + f4 * 4;
    asm volatile("red.global.add.v4.f32 [%0], {%1,%2,%3,%4};"
                 :: "l"(p), "f"(ev * hv.x), "f"(ev * hv.y),
                    "f"(ev * hv.z), "f"(ev * hv.w)
                 : "memory");
}

// ---------------------------------------------------------------------------
// Finalize: out = relu(out / rowsum)
// ---------------------------------------------------------------------------
__global__ void fin_kernel(float* __restrict__ out, int N) {
    int idx = blockIdx.x * blockDim.x + threadIdx.x;
    int total = N * (F / 4);
    if (idx >= total) return;
    float r = g_rowsum[idx / (F / 4)];
    float inv = 1.0f / r;
    float4 v = reinterpret_cast<float4*>(out)[idx];
    v.x = fmaxf(v.x * inv, 0.f);
    v.y = fmaxf(v.y * inv, 0.f);
    v.z = fmaxf(v.z * inv, 0.f);
    v.w = fmaxf(v.w * inv, 0.f);
    reinterpret_cast<float4*>(out)[idx] = v;
}

// ---------------------------------------------------------------------------
extern "C" void kernel_launch(void* const* d_in, const int* in_sizes, int n_in,
                              void* d_out, int out_size) {
    const float* x    = (const float*)d_in[0];
    const int*   edge = (const int*)d_in[1];
    const float* W    = (const float*)d_in[2];
    const float* a    = (const float*)d_in[3];
    float* out = (float*)d_out;

    int N = in_sizes[0] / F;
    int E = in_sizes[1] / 2;

    // Zero accumulators (graph-capturable memset nodes)
    void* rowsum_ptr = nullptr;
    cudaGetSymbolAddress(&rowsum_ptr, g_rowsum);
    cudaMemsetAsync(d_out, 0, (size_t)N * F * sizeof(float), 0);
    cudaMemsetAsync(rowsum_ptr, 0, (size_t)N * sizeof(float), 0);

    // 1. h = x @ W
    dim3 ggrid(F / BN, (N + BM - 1) / BM);
    gemm_kernel<<<ggrid, 256>>>(x, W, N);

    // 2. s, t projections
    st_kernel<<<(N + 7) / 8, 256>>>(a, N);

    // 3. per-edge attention + rowsum
    edge_kernel<<<(E + 255) / 256, 256>>>(edge, E);

    // 4. message scatter
    msg_kernel<<<(E + 3) / 4, 256>>>(edge, out, E);

    // 5. normalize + relu
    fin_kernel<<<(N * (F / 4) + 255) / 256, 256>>>(out, N);
}

// round 2
// speedup vs baseline: 1.5113x; 1.5113x over previous
#include <cuda_runtime.h>
#include <cuda_bf16.h>

#define NMAX 50000
#define EMAX 850000
#define F 256
#define ALPHA 0.2f
#define SCAN_B 256
#define NB_MAX ((NMAX + SCAN_B - 1) / SCAN_B)   // 196

// Scratch (__device__ globals — allocation-free rule)
__device__ float g_h[NMAX * F];      // h = x @ W
__device__ float g_s[NMAX];          // h @ a[:F]
__device__ float g_t[NMAX];          // h @ a[F:]
__device__ int   g_count[NMAX];      // out-degree per src
__device__ int   g_off[NMAX];        // CSR row offsets (exclusive)
__device__ int   g_cursor[NMAX];     // scatter cursors
__device__ int   g_csr_dst[EMAX];    // dst ids grouped by src
__device__ int   g_bsum[SCAN_B];     // per-block sums for scan
__device__ int   g_bsumex[SCAN_B];   // exclusive-scanned block sums

// ---------------------------------------------------------------------------
// GEMM: h = x @ W, with fused s/t projection epilogue (atomicAdd partials).
// 64x64 tile, BK=32, 4x4 per-thread, 256 threads.
// ---------------------------------------------------------------------------
#define BM 64
#define BN 64
#define BK 32

__global__ void gemm_st_kernel(const float* __restrict__ A,
                               const float* __restrict__ B,
                               const float* __restrict__ a,
                               int M) {
    __shared__ float As[BK][BM];
    __shared__ float Bs[BK][BN];

    const int bm = blockIdx.y * BM;
    const int bn = blockIdx.x * BN;
    const int tid = threadIdx.x;
    const int tx = tid & 15;
    const int ty = tid >> 4;

    float acc[4][4] = {};

    for (int k0 = 0; k0 < F; k0 += BK) {
        #pragma unroll
        for (int i = 0; i < 2; i++) {
            int idx = tid + i * 256;
            int row = idx >> 3;
            int kc4 = idx & 7;
            float4 v = make_float4(0.f, 0.f, 0.f, 0.f);
            if (bm + row < M)
                v = *reinterpret_cast<const float4*>(&A[(size_t)(bm + row) * F + k0 + kc4 * 4]);
            As[kc4 * 4 + 0][row] = v.x;
            As[kc4 * 4 + 1][row] = v.y;
            As[kc4 * 4 + 2][row] = v.z;
            As[kc4 * 4 + 3][row] = v.w;
        }
        #pragma unroll
        for (int i = 0; i < 2; i++) {
            int idx = tid + i * 256;
            int kr  = idx >> 4;
            int nc4 = idx & 15;
            float4 v = *reinterpret_cast<const float4*>(&B[(size_t)(k0 + kr) * F + bn + nc4 * 4]);
            reinterpret_cast<float4*>(&Bs[kr][0])[nc4] = v;
        }
        __syncthreads();

        #pragma unroll
        for (int k = 0; k < BK; k++) {
            float4 a4 = *reinterpret_cast<float4*>(&As[k][ty * 4]);
            float4 b4 = reinterpret_cast<float4*>(&Bs[k][0])[tx];
            float av[4] = {a4.x, a4.y, a4.z, a4.w};
            float bv[4] = {b4.x, b4.y, b4.z, b4.w};
            #pragma unroll
            for (int i = 0; i < 4; i++)
                #pragma unroll
                for (int j = 0; j < 4; j++)
                    acc[i][j] += av[i] * bv[j];
        }
        __syncthreads();
    }

    // Epilogue: write h tile + fused partial s/t dot products.
    float4 a1 = *reinterpret_cast<const float4*>(&a[bn + tx * 4]);
    float4 a2 = *reinterpret_cast<const float4*>(&a[F + bn + tx * 4]);

    #pragma unroll
    for (int i = 0; i < 4; i++) {
        int row = bm + ty * 4 + i;
        bool ok = row < M;
        if (ok) {
            float4 v = make_float4(acc[i][0], acc[i][1], acc[i][2], acc[i][3]);
            *reinterpret_cast<float4*>(&g_h[(size_t)row * F + bn + tx * 4]) = v;
        }
        float sp = acc[i][0] * a1.x + acc[i][1] * a1.y + acc[i][2] * a1.z + acc[i][3] * a1.w;
        float tp = acc[i][0] * a2.x + acc[i][1] * a2.y + acc[i][2] * a2.z + acc[i][3] * a2.w;
        // reduce across the 16 tx lanes (lane = (ty&1)*16 + tx → xor 1,2,4,8 stays in group)
        #pragma unroll
        for (int off = 8; off > 0; off >>= 1) {
            sp += __shfl_xor_sync(0xFFFFFFFF, sp, off);
            tp += __shfl_xor_sync(0xFFFFFFFF, tp, off);
        }
        if (tx == 0 && ok) {
            atomicAdd(&g_s[row], sp);
            atomicAdd(&g_t[row], tp);
        }
    }
}

// ---------------------------------------------------------------------------
// CSR build: histogram -> block sums -> top scan -> offsets -> scatter
// ---------------------------------------------------------------------------
__global__ void hist_kernel(const int* __restrict__ edge, int E) {
    int i = blockIdx.x * blockDim.x + threadIdx.x;
    if (i < E) atomicAdd(&g_count[edge[i]], 1);
}

__global__ void bsum_kernel(int N) {
    __shared__ int sd[SCAN_B];
    int i = blockIdx.x * SCAN_B + threadIdx.x;
    sd[threadIdx.x] = (i < N) ? g_count[i] : 0;
    __syncthreads();
    #pragma unroll
    for (int d = SCAN_B / 2; d > 0; d >>= 1) {
        if (threadIdx.x < d) sd[threadIdx.x] += sd[threadIdx.x + d];
        __syncthreads();
    }
    if (threadIdx.x == 0) g_bsum[blockIdx.x] = sd[0];
}

__global__ void scan_top_kernel(int nb) {
    __shared__ int sd[SCAN_B];
    int t = threadIdx.x;
    sd[t] = (t < nb) ? g_bsum[t] : 0;
    __syncthreads();
    #pragma unroll
    for (int d = 1; d < SCAN_B; d <<= 1) {
        int v = (t >= d) ? sd[t - d] : 0;
        __syncthreads();
        sd[t] += v;
        __syncthreads();
    }
    int incl = sd[t];
    int own = (t < nb) ? g_bsum[t] : 0;
    if (t < nb) g_bsumex[t] = incl - own;   // exclusive
}

__global__ void offsets_kernel(int N) {
    __shared__ int sd[SCAN_B];
    int t = threadIdx.x;
    int i = blockIdx.x * SCAN_B + t;
    int c = (i < N) ? g_count[i] : 0;
    sd[t] = c;
    __syncthreads();
    #pragma unroll
    for (int d = 1; d < SCAN_B; d <<= 1) {
        int v = (t >= d) ? sd[t - d] : 0;
        __syncthreads();
        sd[t] += v;
        __syncthreads();
    }
    if (i < N) {
        int excl = g_bsumex[blockIdx.x] + sd[t] - c;
        g_off[i] = excl;
        g_cursor[i] = excl;
    }
}

__global__ void scatter_kernel(const int* __restrict__ edge, int E) {
    int i = blockIdx.x * blockDim.x + threadIdx.x;
    if (i >= E) return;
    int src = edge[i];
    int dst = edge[E + i];
    int pos = atomicAdd(&g_cursor[src], 1);
    g_csr_dst[pos] = dst;
}

// ---------------------------------------------------------------------------
// Fused aggregation: one 64-thread block per node.
//   acc[f] = sum_j e_j * h[dst_j][f] ;  rowsum = sum_j e_j
//   out[node] = relu(acc / rowsum)
// ---------------------------------------------------------------------------
__device__ __forceinline__ float att(float s_src, int dst) {
    float logit = s_src + g_t[dst];
    float l = logit > 0.f ? logit : ALPHA * logit;
    return expf(-l);
}

__global__ void agg_kernel(float* __restrict__ out, int N) {
    int node = blockIdx.x;
    int f4 = threadIdx.x;                    // 0..63 (float4 lane)
    int beg = g_off[node];
    int deg = g_count[node];
    float s_src = g_s[node];

    float4 acc = make_float4(0.f, 0.f, 0.f, 0.f);
    float rowsum = 0.f;

    int j = 0;
    for (; j + 4 <= deg; j += 4) {
        int d0 = g_csr_dst[beg + j + 0];
        int d1 = g_csr_dst[beg + j + 1];
        int d2 = g_csr_dst[beg + j + 2];
        int d3 = g_csr_dst[beg + j + 3];
        float e0 = att(s_src, d0);
        float e1 = att(s_src, d1);
        float e2 = att(s_src, d2);
        float e3 = att(s_src, d3);
        float4 h0 = reinterpret_cast<const float4*>(&g_h[(size_t)d0 * F])[f4];
        float4 h1 = reinterpret_cast<const float4*>(&g_h[(size_t)d1 * F])[f4];
        float4 h2 = reinterpret_cast<const float4*>(&g_h[(size_t)d2 * F])[f4];
        float4 h3 = reinterpret_cast<const float4*>(&g_h[(size_t)d3 * F])[f4];
        rowsum += (e0 + e1) + (e2 + e3);
        acc.x += e0 * h0.x + e1 * h1.x + e2 * h2.x + e3 * h3.x;
        acc.y += e0 * h0.y + e1 * h1.y + e2 * h2.y + e3 * h3.y;
        acc.z += e0 * h0.z + e1 * h1.z + e2 * h2.z + e3 * h3.z;
        acc.w += e0 * h0.w + e1 * h1.w + e2 * h2.w + e3 * h3.w;
    }
    for (; j < deg; j++) {
        int d = g_csr_dst[beg + j];
        float e = att(s_src, d);
        float4 hv = reinterpret_cast<const float4*>(&g_h[(size_t)d * F])[f4];
        rowsum += e;
        acc.x += e * hv.x;
        acc.y += e * hv.y;
        acc.z += e * hv.z;
        acc.w += e * hv.w;
    }

    float inv = 1.0f / rowsum;
    float4 v;
    v.x = fmaxf(acc.x * inv, 0.f);
    v.y = fmaxf(acc.y * inv, 0.f);
    v.z = fmaxf(acc.z * inv, 0.f);
    v.w = fmaxf(acc.w * inv, 0.f);
    reinterpret_cast<float4*>(&out[(size_t)node * F])[f4] = v;
}

// ---------------------------------------------------------------------------
extern "C" void kernel_launch(void* const* d_in, const int* in_sizes, int n_in,
                              void* d_out, int out_size) {
    const float* x    = (const float*)d_in[0];
    const int*   edge = (const int*)d_in[1];
    const float* W    = (const float*)d_in[2];
    const float* a    = (const float*)d_in[3];
    float* out = (float*)d_out;

    int N = in_sizes[0] / F;
    int E = in_sizes[1] / 2;
    int nb = (N + SCAN_B - 1) / SCAN_B;

    void *p_count, *p_s, *p_t;
    cudaGetSymbolAddress(&p_count, g_count);
    cudaGetSymbolAddress(&p_s, g_s);
    cudaGetSymbolAddress(&p_t, g_t);
    cudaMemsetAsync(p_count, 0, (size_t)N * sizeof(int), 0);
    cudaMemsetAsync(p_s, 0, (size_t)N * sizeof(float), 0);
    cudaMemsetAsync(p_t, 0, (size_t)N * sizeof(float), 0);

    // GEMM + fused s/t projection
    dim3 ggrid(F / BN, (N + BM - 1) / BM);
    gemm_st_kernel<<<ggrid, 256>>>(x, W, a, N);

    // CSR build
    hist_kernel<<<(E + 255) / 256, 256>>>(edge, E);
    bsum_kernel<<<nb, SCAN_B>>>(N);
    scan_top_kernel<<<1, SCAN_B>>>(nb);
    offsets_kernel<<<nb, SCAN_B>>>(N);
    scatter_kernel<<<(E + 255) / 256, 256>>>(edge, E);

    // Fused attention + aggregation + normalize + relu
    agg_kernel<<<N, 64>>>(out, N);
}

// round 5
// speedup vs baseline: 2.2574x; 1.4937x over previous
#include <cuda_runtime.h>
#include <cuda_bf16.h>
#include <cstdint>

#define NMAX 50000
#define EMAX 850000
#define F 256
#define ALPHA 0.2f
#define SCAN_B 256

// ---------------------------------------------------------------------------
// Scratch (__device__ globals — allocation-free rule)
// ---------------------------------------------------------------------------
__device__ float g_h[NMAX * F];            // h = x @ W (fp32)
__device__ float g_s[NMAX];                // h @ a[:F]
__device__ float g_t[NMAX];                // h @ a[F:]
__device__ __nv_bfloat16 g_xhi[NMAX * F];  // bf16 split of x (row-major [N][K])
__device__ __nv_bfloat16 g_xlo[NMAX * F];
__device__ __nv_bfloat16 g_wthi[F * F];    // W^T bf16 split ([n][k] K-major)
__device__ __nv_bfloat16 g_wtlo[F * F];
__device__ int g_count[NMAX];
__device__ int g_off[NMAX];
__device__ int g_cursor[NMAX];
__device__ int g_csr_dst[EMAX];
__device__ int g_bsum[SCAN_B];
__device__ int g_bsumex[SCAN_B];

// ---------------------------------------------------------------------------
// Convert kernels: fp32 -> (bf16 hi, bf16 lo) split
// ---------------------------------------------------------------------------
__global__ void convert_x_kernel(const float* __restrict__ x, int total4) {
    int i = blockIdx.x * blockDim.x + threadIdx.x;
    if (i >= total4) return;
    float4 v = reinterpret_cast<const float4*>(x)[i];
    __nv_bfloat16 hx = __float2bfloat16(v.x), hy = __float2bfloat16(v.y);
    __nv_bfloat16 hz = __float2bfloat16(v.z), hw = __float2bfloat16(v.w);
    __nv_bfloat162 hi0, hi1, lo0, lo1;
    hi0.x = hx; hi0.y = hy; hi1.x = hz; hi1.y = hw;
    lo0.x = __float2bfloat16(v.x - __bfloat162float(hx));
    lo0.y = __float2bfloat16(v.y - __bfloat162float(hy));
    lo1.x = __float2bfloat16(v.z - __bfloat162float(hz));
    lo1.y = __float2bfloat16(v.w - __bfloat162float(hw));
    reinterpret_cast<__nv_bfloat162*>(g_xhi)[i * 2 + 0] = hi0;
    reinterpret_cast<__nv_bfloat162*>(g_xhi)[i * 2 + 1] = hi1;
    reinterpret_cast<__nv_bfloat162*>(g_xlo)[i * 2 + 0] = lo0;
    reinterpret_cast<__nv_bfloat162*>(g_xlo)[i * 2 + 1] = lo1;
}

__global__ void convert_w_kernel(const float* __restrict__ W) {
    int i = blockIdx.x * blockDim.x + threadIdx.x;  // i = n*256 + k
    if (i >= F * F) return;
    int n = i >> 8, k = i & 255;
    float v = W[k * F + n];
    __nv_bfloat16 h = __float2bfloat16(v);
    g_wthi[i] = h;
    g_wtlo[i] = __float2bfloat16(v - __bfloat162float(h));
}

// ---------------------------------------------------------------------------
// mma.sync bf16 GEMM: h = x @ W (3-product split), fused s/t epilogue.
// CTA: 64(M) x 256(N), K chunks of 64. 256 threads = 8 warps (2 M x 4 N).
// Warp tile: 32(M) x 64(N). m16n8k16, fp32 accum.
// ---------------------------------------------------------------------------
__device__ __forceinline__ uint32_t smem_u32(const void* p) {
    uint32_t a;
    asm("{ .reg .u64 t; cvta.to.shared.u64 t, %1; cvt.u32.u64 %0, t; }" : "=r"(a) : "l"(p));
    return a;
}

__device__ __forceinline__ void ldsm_x4(uint32_t addr, uint32_t& r0, uint32_t& r1,
                                        uint32_t& r2, uint32_t& r3) {
    asm volatile("ldmatrix.sync.aligned.m8n8.x4.shared.b16 {%0,%1,%2,%3}, [%4];"
                 : "=r"(r0), "=r"(r1), "=r"(r2), "=r"(r3) : "r"(addr));
}

__device__ __forceinline__ void mma_bf16(float* d, const uint32_t* a, uint32_t b0, uint32_t b1) {
    asm volatile("mma.sync.aligned.m16n8k16.row.col.f32.bf16.bf16.f32 "
                 "{%0,%1,%2,%3}, {%4,%5,%6,%7}, {%8,%9}, {%0,%1,%2,%3};"
                 : "+f"(d[0]), "+f"(d[1]), "+f"(d[2]), "+f"(d[3])
                 : "r"(a[0]), "r"(a[1]), "r"(a[2]), "r"(a[3]), "r"(b0), "r"(b1));
}

#define GBM 64
#define ROWB 144                     // smem row stride bytes (72 bf16, pad)
#define SM_SRED 0                    // 64 floats
#define SM_TRED 256                  // 64 floats
#define SM_A_HI 512                  // 64 * 144 = 9216
#define SM_A_LO (SM_A_HI + 9216)
#define SM_B_HI (SM_A_LO + 9216)     // 256 * 144 = 36864
#define SM_B_LO (SM_B_HI + 36864)
#define SM_GEMM_TOTAL (SM_B_LO + 36864)   // 92672

__global__ void __launch_bounds__(256, 1) gemm_mma_kernel(const float* __restrict__ a, int M) {
    extern __shared__ char smem[];
    const uint32_t sbase = smem_u32(smem);
    const int tid = threadIdx.x;
    const int wid = tid >> 5;
    const int lane = tid & 31;
    const int wm = wid >> 2;          // 0..1
    const int wn = wid & 3;           // 0..3
    const int bm = blockIdx.x * GBM;

    float* s_red = reinterpret_cast<float*>(smem + SM_SRED);
    float* t_red = reinterpret_cast<float*>(smem + SM_TRED);
    if (tid < 64) { s_red[tid] = 0.f; t_red[tid] = 0.f; }

    float acc[2][8][4];
    #pragma unroll
    for (int mf = 0; mf < 2; mf++)
        #pragma unroll
        for (int nf = 0; nf < 8; nf++)
            #pragma unroll
            for (int j = 0; j < 4; j++) acc[mf][nf][j] = 0.f;

    const uint4* xhi4 = reinterpret_cast<const uint4*>(g_xhi);
    const uint4* xlo4 = reinterpret_cast<const uint4*>(g_xlo);
    const uint4* whi4 = reinterpret_cast<const uint4*>(g_wthi);
    const uint4* wlo4 = reinterpret_cast<const uint4*>(g_wtlo);
    const uint4 z4 = make_uint4(0, 0, 0, 0);

    // ldmatrix per-lane addressing offsets
    const int lr = lane & 15;          // row within 16-row tile
    const int lc = (lane >> 4) * 16;   // byte offset of 8-col half

    for (int c = 0; c < 4; c++) {
        // stage A (64 rows x 64 bf16, hi+lo)
        #pragma unroll
        for (int i = tid; i < 512; i += 256) {
            int row = i >> 3, q = i & 7;
            int grow = bm + row;
            uint4 vh = z4, vl = z4;
            if (grow < M) {
                int gi = grow * 32 + c * 8 + q;
                vh = xhi4[gi];
                vl = xlo4[gi];
            }
            *reinterpret_cast<uint4*>(smem + SM_A_HI + row * ROWB + q * 16) = vh;
            *reinterpret_cast<uint4*>(smem + SM_A_LO + row * ROWB + q * 16) = vl;
        }
        // stage B (256 n-rows x 64 bf16 K, hi+lo)
        #pragma unroll
        for (int i = tid; i < 2048; i += 256) {
            int n = i >> 3, q = i & 7;
            int gi = n * 32 + c * 8 + q;
            *reinterpret_cast<uint4*>(smem + SM_B_HI + n * ROWB + q * 16) = whi4[gi];
            *reinterpret_cast<uint4*>(smem + SM_B_LO + n * ROWB + q * 16) = wlo4[gi];
        }
        __syncthreads();

        #pragma unroll
        for (int ks = 0; ks < 4; ks++) {
            const uint32_t coff = (uint32_t)(ks * 32 + lc);
            uint32_t ah[2][4], al[2][4];
            #pragma unroll
            for (int mf = 0; mf < 2; mf++) {
                uint32_t arow = (uint32_t)(wm * 32 + mf * 16 + lr) * ROWB + coff;
                ldsm_x4(sbase + SM_A_HI + arow, ah[mf][0], ah[mf][1], ah[mf][2], ah[mf][3]);
                ldsm_x4(sbase + SM_A_LO + arow, al[mf][0], al[mf][1], al[mf][2], al[mf][3]);
            }
            #pragma unroll
            for (int nf2 = 0; nf2 < 4; nf2++) {
                uint32_t brow = (uint32_t)(wn * 64 + nf2 * 16 + lr) * ROWB + coff;
                uint32_t bh0, bh1, bh2, bh3, bl0, bl1, bl2, bl3;
                ldsm_x4(sbase + SM_B_HI + brow, bh0, bh1, bh2, bh3);
                ldsm_x4(sbase + SM_B_LO + brow, bl0, bl1, bl2, bl3);
                #pragma unroll
                for (int mf = 0; mf < 2; mf++) {
                    // n-frag even: {r0, r2}, odd: {r1, r3}
                    mma_bf16(acc[mf][nf2 * 2 + 0], ah[mf], bh0, bh2);
                    mma_bf16(acc[mf][nf2 * 2 + 0], ah[mf], bl0, bl2);
                    mma_bf16(acc[mf][nf2 * 2 + 0], al[mf], bh0, bh2);
                    mma_bf16(acc[mf][nf2 * 2 + 1], ah[mf], bh1, bh3);
                    mma_bf16(acc[mf][nf2 * 2 + 1], ah[mf], bl1, bl3);
                    mma_bf16(acc[mf][nf2 * 2 + 1], al[mf], bh1, bh3);
                }
            }
        }
        __syncthreads();
    }

    // ---- epilogue: store h + fused s/t ----
    // acc[mf][nf][j]: row = bm + wm*32 + mf*16 + (j>>1)*8 + (lane>>2)
    //                 col = wn*64 + nf*8 + (lane&3)*2 + (j&1)
    float av[16], atv[16];
    #pragma unroll
    for (int nf = 0; nf < 8; nf++)
        #pragma unroll
        for (int j = 0; j < 2; j++) {
            int col = wn * 64 + nf * 8 + (lane & 3) * 2 + j;
            av[nf * 2 + j] = a[col];
            atv[nf * 2 + j] = a[F + col];
        }

    #pragma unroll
    for (int mf = 0; mf < 2; mf++) {
        #pragma unroll
        for (int rg = 0; rg < 2; rg++) {
            int rloc = wm * 32 + mf * 16 + rg * 8 + (lane >> 2);
            int grow = bm + rloc;
            bool ok = grow < M;
            float sp = 0.f, tp = 0.f;
            #pragma unroll
            for (int nf = 0; nf < 8; nf++) {
                float d0 = acc[mf][nf][rg * 2 + 0];
                float d1 = acc[mf][nf][rg * 2 + 1];
                sp += d0 * av[nf * 2] + d1 * av[nf * 2 + 1];
                tp += d0 * atv[nf * 2] + d1 * atv[nf * 2 + 1];
                if (ok) {
                    int col = wn * 64 + nf * 8 + (lane & 3) * 2;
                    *reinterpret_cast<float2*>(&g_h[(size_t)grow * F + col]) =
                        make_float2(d0, d1);
                }
            }
            sp += __shfl_xor_sync(0xFFFFFFFF, sp, 1);
            sp += __shfl_xor_sync(0xFFFFFFFF, sp, 2);
            tp += __shfl_xor_sync(0xFFFFFFFF, tp, 1);
            tp += __shfl_xor_sync(0xFFFFFFFF, tp, 2);
            if ((lane & 3) == 0) {
                atomicAdd(&s_red[rloc], sp);
                atomicAdd(&t_red[rloc], tp);
            }
        }
    }
    __syncthreads();
    if (tid < 64 && bm + tid < M) {
        g_s[bm + tid] = s_red[tid];
        g_t[bm + tid] = t_red[tid];
    }
}

// ---------------------------------------------------------------------------
// CSR build: histogram -> block sums -> top scan -> offsets -> scatter
// ---------------------------------------------------------------------------
__global__ void hist_kernel(const int* __restrict__ edge, int E) {
    int i = blockIdx.x * blockDim.x + threadIdx.x;
    if (i < E) atomicAdd(&g_count[edge[i]], 1);
}

__global__ void bsum_kernel(int N) {
    __shared__ int sd[SCAN_B];
    int i = blockIdx.x * SCAN_B + threadIdx.x;
    sd[threadIdx.x] = (i < N) ? g_count[i] : 0;
    __syncthreads();
    #pragma unroll
    for (int d = SCAN_B / 2; d > 0; d >>= 1) {
        if (threadIdx.x < d) sd[threadIdx.x] += sd[threadIdx.x + d];
        __syncthreads();
    }
    if (threadIdx.x == 0) g_bsum[blockIdx.x] = sd[0];
}

__global__ void scan_top_kernel(int nb) {
    __shared__ int sd[SCAN_B];
    int t = threadIdx.x;
    sd[t] = (t < nb) ? g_bsum[t] : 0;
    __syncthreads();
    #pragma unroll
    for (int d = 1; d < SCAN_B; d <<= 1) {
        int v = (t >= d) ? sd[t - d] : 0;
        __syncthreads();
        sd[t] += v;
        __syncthreads();
    }
    int incl = sd[t];
    int own = (t < nb) ? g_bsum[t] : 0;
    if (t < nb) g_bsumex[t] = incl - own;
}

__global__ void offsets_kernel(int N) {
    __shared__ int sd[SCAN_B];
    int t = threadIdx.x;
    int i = blockIdx.x * SCAN_B + t;
    int c = (i < N) ? g_count[i] : 0;
    sd[t] = c;
    __syncthreads();
    #pragma unroll
    for (int d = 1; d < SCAN_B; d <<= 1) {
        int v = (t >= d) ? sd[t - d] : 0;
        __syncthreads();
        sd[t] += v;
        __syncthreads();
    }
    if (i < N) {
        int excl = g_bsumex[blockIdx.x] + sd[t] - c;
        g_off[i] = excl;
        g_cursor[i] = excl;
    }
}

__global__ void scatter_kernel(const int* __restrict__ edge, int E) {
    int i = blockIdx.x * blockDim.x + threadIdx.x;
    if (i >= E) return;
    int src = edge[i];
    int dst = edge[E + i];
    int pos = atomicAdd(&g_cursor[src], 1);
    g_csr_dst[pos] = dst;
}

// ---------------------------------------------------------------------------
// Fused aggregation: one 64-thread block per node (gather formulation)
// ---------------------------------------------------------------------------
__device__ __forceinline__ float att(float s_src, int dst) {
    float logit = s_src + g_t[dst];
    float l = logit > 0.f ? logit : ALPHA * logit;
    return expf(-l);
}

__global__ void agg_kernel(float* __restrict__ out, int N) {
    int node = blockIdx.x;
    int f4 = threadIdx.x;
    int beg = g_off[node];
    int deg = g_count[node];
    float s_src = g_s[node];

    float4 acc = make_float4(0.f, 0.f, 0.f, 0.f);
    float rowsum = 0.f;

    int j = 0;
    for (; j + 4 <= deg; j += 4) {
        int d0 = g_csr_dst[beg + j + 0];
        int d1 = g_csr_dst[beg + j + 1];
        int d2 = g_csr_dst[beg + j + 2];
        int d3 = g_csr_dst[beg + j + 3];
        float e0 = att(s_src, d0);
        float e1 = att(s_src, d1);
        float e2 = att(s_src, d2);
        float e3 = att(s_src, d3);
        float4 h0 = reinterpret_cast<const float4*>(&g_h[(size_t)d0 * F])[f4];
        float4 h1 = reinterpret_cast<const float4*>(&g_h[(size_t)d1 * F])[f4];
        float4 h2 = reinterpret_cast<const float4*>(&g_h[(size_t)d2 * F])[f4];
        float4 h3 = reinterpret_cast<const float4*>(&g_h[(size_t)d3 * F])[f4];
        rowsum += (e0 + e1) + (e2 + e3);
        acc.x += e0 * h0.x + e1 * h1.x + e2 * h2.x + e3 * h3.x;
        acc.y += e0 * h0.y + e1 * h1.y + e2 * h2.y + e3 * h3.y;
        acc.z += e0 * h0.z + e1 * h1.z + e2 * h2.z + e3 * h3.z;
        acc.w += e0 * h0.w + e1 * h1.w + e2 * h2.w + e3 * h3.w;
    }
    for (; j < deg; j++) {
        int d = g_csr_dst[beg + j];
        float e = att(s_src, d);
        float4 hv = reinterpret_cast<const float4*>(&g_h[(size_t)d * F])[f4];
        rowsum += e;
        acc.x += e * hv.x;
        acc.y += e * hv.y;
        acc.z += e * hv.z;
        acc.w += e * hv.w;
    }

    float inv = 1.0f / rowsum;
    float4 v;
    v.x = fmaxf(acc.x * inv, 0.f);
    v.y = fmaxf(acc.y * inv, 0.f);
    v.z = fmaxf(acc.z * inv, 0.f);
    v.w = fmaxf(acc.w * inv, 0.f);
    reinterpret_cast<float4*>(&out[(size_t)node * F])[f4] = v;
}

// ---------------------------------------------------------------------------
extern "C" void kernel_launch(void* const* d_in, const int* in_sizes, int n_in,
                              void* d_out, int out_size) {
    const float* x    = (const float*)d_in[0];
    const int*   edge = (const int*)d_in[1];
    const float* W    = (const float*)d_in[2];
    const float* a    = (const float*)d_in[3];
    float* out = (float*)d_out;

    int N = in_sizes[0] / F;
    int E = in_sizes[1] / 2;
    int nb = (N + SCAN_B - 1) / SCAN_B;

    cudaFuncSetAttribute(gemm_mma_kernel, cudaFuncAttributeMaxDynamicSharedMemorySize,
                         SM_GEMM_TOTAL);

    void* p_count;
    cudaGetSymbolAddress(&p_count, g_count);
    cudaMemsetAsync(p_count, 0, (size_t)N * sizeof(int), 0);

    // bf16 splits
    convert_x_kernel<<<(N * (F / 4) + 255) / 256, 256>>>(x, N * (F / 4));
    convert_w_kernel<<<(F * F + 255) / 256, 256>>>(W);

    // tensor-core GEMM + fused s/t
    gemm_mma_kernel<<<(N + GBM - 1) / GBM, 256, SM_GEMM_TOTAL>>>(a, N);

    // CSR build
    hist_kernel<<<(E + 255) / 256, 256>>>(edge, E);
    bsum_kernel<<<nb, SCAN_B>>>(N);
    scan_top_kernel<<<1, SCAN_B>>>(nb);
    offsets_kernel<<<nb, SCAN_B>>>(N);
    scatter_kernel<<<(E + 255) / 256, 256>>>(edge, E);

    // Fused attention + aggregation + normalize + relu
    agg_kernel<<<N, 64>>>(out, N);
}

// round 7
// speedup vs baseline: 2.4908x; 1.1034x over previous
#include <cuda_runtime.h>
#include <cuda_bf16.h>
#include <cuda_fp16.h>
#include <cstdint>

#define NMAX 50000
#define EMAX 850000
#define F 256
#define ALPHA 0.2f
#define SCAN_B 256

// ---------------------------------------------------------------------------
// Scratch (__device__ globals — allocation-free rule)
// ---------------------------------------------------------------------------
__device__ __half g_hf16[NMAX * F];        // h = x @ W (fp16, gather payload)
__device__ float g_s[NMAX];                // h @ a[:F]
__device__ float g_t[NMAX];                // h @ a[F:]
__device__ __nv_bfloat16 g_wthi[F * F];    // W^T bf16 split ([n][k] K-major)
__device__ __nv_bfloat16 g_wtlo[F * F];
__device__ int g_count[NMAX];
__device__ int g_off[NMAX];
__device__ int g_cursor[NMAX];
__device__ int g_csr_dst[EMAX];
__device__ int g_bsum[SCAN_B];
__device__ int g_bsumex[SCAN_B];

// ---------------------------------------------------------------------------
// W transpose + bf16 split (tiny: 256KB)
// ---------------------------------------------------------------------------
__global__ void convert_w_kernel(const float* __restrict__ W) {
    int i = blockIdx.x * blockDim.x + threadIdx.x;  // i = n*256 + k
    if (i >= F * F) return;
    int n = i >> 8, k = i & 255;
    float v = W[k * F + n];
    __nv_bfloat16 h = __float2bfloat16(v);
    g_wthi[i] = h;
    g_wtlo[i] = __float2bfloat16(v - __bfloat162float(h));
}

// ---------------------------------------------------------------------------
// mma.sync bf16 GEMM: h = x @ W (3-product split), fused s/t epilogue.
// CTA: 64(M) x 256(N), K chunks of 64. 256 threads = 8 warps (2 M x 4 N).
// A staged directly from fp32 x with in-register hi/lo split.
// ---------------------------------------------------------------------------
__device__ __forceinline__ uint32_t smem_u32(const void* p) {
    uint32_t a;
    asm("{ .reg .u64 t; cvta.to.shared.u64 t, %1; cvt.u32.u64 %0, t; }" : "=r"(a) : "l"(p));
    return a;
}

__device__ __forceinline__ void ldsm_x4(uint32_t addr, uint32_t& r0, uint32_t& r1,
                                        uint32_t& r2, uint32_t& r3) {
    asm volatile("ldmatrix.sync.aligned.m8n8.x4.shared.b16 {%0,%1,%2,%3}, [%4];"
                 : "=r"(r0), "=r"(r1), "=r"(r2), "=r"(r3) : "r"(addr));
}

__device__ __forceinline__ void mma_bf16(float* d, const uint32_t* a, uint32_t b0, uint32_t b1) {
    asm volatile("mma.sync.aligned.m16n8k16.row.col.f32.bf16.bf16.f32 "
                 "{%0,%1,%2,%3}, {%4,%5,%6,%7}, {%8,%9}, {%0,%1,%2,%3};"
                 : "+f"(d[0]), "+f"(d[1]), "+f"(d[2]), "+f"(d[3])
                 : "r"(a[0]), "r"(a[1]), "r"(a[2]), "r"(a[3]), "r"(b0), "r"(b1));
}

#define GBM 64
#define ROWB 144                     // smem row stride bytes (64 bf16 + pad)
#define SM_SRED 0                    // 64 floats
#define SM_TRED 256                  // 64 floats
#define SM_A_HI 512                  // 64 * 144 = 9216
#define SM_A_LO (SM_A_HI + 9216)
#define SM_B_HI (SM_A_LO + 9216)     // 256 * 144 = 36864
#define SM_B_LO (SM_B_HI + 36864)
#define SM_GEMM_TOTAL (SM_B_LO + 36864)   // 92672

__global__ void __launch_bounds__(256, 1) gemm_mma_kernel(const float* __restrict__ x,
                                                          const float* __restrict__ a, int M) {
    extern __shared__ char smem[];
    const uint32_t sbase = smem_u32(smem);
    const int tid = threadIdx.x;
    const int wid = tid >> 5;
    const int lane = tid & 31;
    const int wm = wid >> 2;          // 0..1
    const int wn = wid & 3;           // 0..3
    const int bm = blockIdx.x * GBM;

    float* s_red = reinterpret_cast<float*>(smem + SM_SRED);
    float* t_red = reinterpret_cast<float*>(smem + SM_TRED);
    if (tid < 64) { s_red[tid] = 0.f; t_red[tid] = 0.f; }

    float acc[2][8][4];
    #pragma unroll
    for (int mf = 0; mf < 2; mf++)
        #pragma unroll
        for (int nf = 0; nf < 8; nf++)
            #pragma unroll
            for (int j = 0; j < 4; j++) acc[mf][nf][j] = 0.f;

    const float4* x4 = reinterpret_cast<const float4*>(x);
    const uint4* whi4 = reinterpret_cast<const uint4*>(g_wthi);
    const uint4* wlo4 = reinterpret_cast<const uint4*>(g_wtlo);

    const int lr = lane & 15;
    const int lc = (lane >> 4) * 16;

    for (int c = 0; c < 4; c++) {
        // stage A: 64 rows x 64 fp32 cols, split hi/lo in registers
        #pragma unroll
        for (int i = tid; i < 1024; i += 256) {
            int row = i >> 4, q = i & 15;          // q indexes float4 (4 elems)
            int grow = bm + row;
            float4 v = make_float4(0.f, 0.f, 0.f, 0.f);
            if (grow < M) v = x4[grow * 64 + c * 16 + q];
            __nv_bfloat162 h0, h1, l0, l1;
            h0.x = __float2bfloat16(v.x); h0.y = __float2bfloat16(v.y);
            h1.x = __float2bfloat16(v.z); h1.y = __float2bfloat16(v.w);
            l0.x = __float2bfloat16(v.x - __bfloat162float(h0.x));
            l0.y = __float2bfloat16(v.y - __bfloat162float(h0.y));
            l1.x = __float2bfloat16(v.z - __bfloat162float(h1.x));
            l1.y = __float2bfloat16(v.w - __bfloat162float(h1.y));
            uint32_t off = (uint32_t)(row * ROWB + q * 8);
            *reinterpret_cast<uint2*>(smem + SM_A_HI + off) =
                make_uint2(*reinterpret_cast<uint32_t*>(&h0), *reinterpret_cast<uint32_t*>(&h1));
            *reinterpret_cast<uint2*>(smem + SM_A_LO + off) =
                make_uint2(*reinterpret_cast<uint32_t*>(&l0), *reinterpret_cast<uint32_t*>(&l1));
        }
        // stage B: 256 n-rows x 64 bf16 K (hi+lo)
        #pragma unroll
        for (int i = tid; i < 2048; i += 256) {
            int n = i >> 3, q = i & 7;
            int gi = n * 32 + c * 8 + q;
            *reinterpret_cast<uint4*>(smem + SM_B_HI + n * ROWB + q * 16) = whi4[gi];
            *reinterpret_cast<uint4*>(smem + SM_B_LO + n * ROWB + q * 16) = wlo4[gi];
        }
        __syncthreads();

        #pragma unroll
        for (int ks = 0; ks < 4; ks++) {
            const uint32_t coff = (uint32_t)(ks * 32 + lc);
            uint32_t ah[2][4], al[2][4];
            #pragma unroll
            for (int mf = 0; mf < 2; mf++) {
                uint32_t arow = (uint32_t)(wm * 32 + mf * 16 + lr) * ROWB + coff;
                ldsm_x4(sbase + SM_A_HI + arow, ah[mf][0], ah[mf][1], ah[mf][2], ah[mf][3]);
                ldsm_x4(sbase + SM_A_LO + arow, al[mf][0], al[mf][1], al[mf][2], al[mf][3]);
            }
            #pragma unroll
            for (int nf2 = 0; nf2 < 4; nf2++) {
                uint32_t brow = (uint32_t)(wn * 64 + nf2 * 16 + lr) * ROWB + coff;
                uint32_t bh0, bh1, bh2, bh3, bl0, bl1, bl2, bl3;
                ldsm_x4(sbase + SM_B_HI + brow, bh0, bh1, bh2, bh3);
                ldsm_x4(sbase + SM_B_LO + brow, bl0, bl1, bl2, bl3);
                #pragma unroll
                for (int mf = 0; mf < 2; mf++) {
                    mma_bf16(acc[mf][nf2 * 2 + 0], ah[mf], bh0, bh2);
                    mma_bf16(acc[mf][nf2 * 2 + 0], ah[mf], bl0, bl2);
                    mma_bf16(acc[mf][nf2 * 2 + 0], al[mf], bh0, bh2);
                    mma_bf16(acc[mf][nf2 * 2 + 1], ah[mf], bh1, bh3);
                    mma_bf16(acc[mf][nf2 * 2 + 1], ah[mf], bl1, bl3);
                    mma_bf16(acc[mf][nf2 * 2 + 1], al[mf], bh1, bh3);
                }
            }
        }
        __syncthreads();
    }

    // ---- epilogue: store h (fp16) + fused s/t ----
    float av[16], atv[16];
    #pragma unroll
    for (int nf = 0; nf < 8; nf++)
        #pragma unroll
        for (int j = 0; j < 2; j++) {
            int col = wn * 64 + nf * 8 + (lane & 3) * 2 + j;
            av[nf * 2 + j] = a[col];
            atv[nf * 2 + j] = a[F + col];
        }

    #pragma unroll
    for (int mf = 0; mf < 2; mf++) {
        #pragma unroll
        for (int rg = 0; rg < 2; rg++) {
            int rloc = wm * 32 + mf * 16 + rg * 8 + (lane >> 2);
            int grow = bm + rloc;
            bool ok = grow < M;
            float sp = 0.f, tp = 0.f;
            #pragma unroll
            for (int nf = 0; nf < 8; nf++) {
                float d0 = acc[mf][nf][rg * 2 + 0];
                float d1 = acc[mf][nf][rg * 2 + 1];
                sp += d0 * av[nf * 2] + d1 * av[nf * 2 + 1];
                tp += d0 * atv[nf * 2] + d1 * atv[nf * 2 + 1];
                if (ok) {
                    int col = wn * 64 + nf * 8 + (lane & 3) * 2;
                    *reinterpret_cast<__half2*>(&g_hf16[(size_t)grow * F + col]) =
                        __floats2half2_rn(d0, d1);
                }
            }
            sp += __shfl_xor_sync(0xFFFFFFFF, sp, 1);
            sp += __shfl_xor_sync(0xFFFFFFFF, sp, 2);
            tp += __shfl_xor_sync(0xFFFFFFFF, tp, 1);
            tp += __shfl_xor_sync(0xFFFFFFFF, tp, 2);
            if ((lane & 3) == 0) {
                atomicAdd(&s_red[rloc], sp);
                atomicAdd(&t_red[rloc], tp);
            }
        }
    }
    __syncthreads();
    if (tid < 64 && bm + tid < M) {
        g_s[bm + tid] = s_red[tid];
        g_t[bm + tid] = t_red[tid];
    }
}

// ---------------------------------------------------------------------------
// CSR build: histogram -> block sums -> top scan -> offsets -> scatter
// ---------------------------------------------------------------------------
__global__ void hist_kernel(const int* __restrict__ edge, int E) {
    int i = blockIdx.x * blockDim.x + threadIdx.x;
    if (i < E) atomicAdd(&g_count[edge[i]], 1);
}

__global__ void bsum_kernel(int N) {
    __shared__ int sd[SCAN_B];
    int i = blockIdx.x * SCAN_B + threadIdx.x;
    sd[threadIdx.x] = (i < N) ? g_count[i] : 0;
    __syncthreads();
    #pragma unroll
    for (int d = SCAN_B / 2; d > 0; d >>= 1) {
        if (threadIdx.x < d) sd[threadIdx.x] += sd[threadIdx.x + d];
        __syncthreads();
    }
    if (threadIdx.x == 0) g_bsum[blockIdx.x] = sd[0];
}

__global__ void scan_top_kernel(int nb) {
    __shared__ int sd[SCAN_B];
    int t = threadIdx.x;
    sd[t] = (t < nb) ? g_bsum[t] : 0;
    __syncthreads();
    #pragma unroll
    for (int d = 1; d < SCAN_B; d <<= 1) {
        int v = (t >= d) ? sd[t - d] : 0;
        __syncthreads();
        sd[t] += v;
        __syncthreads();
    }
    int incl = sd[t];
    int own = (t < nb) ? g_bsum[t] : 0;
    if (t < nb) g_bsumex[t] = incl - own;
}

__global__ void offsets_kernel(int N) {
    __shared__ int sd[SCAN_B];
    int t = threadIdx.x;
    int i = blockIdx.x * SCAN_B + t;
    int c = (i < N) ? g_count[i] : 0;
    sd[t] = c;
    __syncthreads();
    #pragma unroll
    for (int d = 1; d < SCAN_B; d <<= 1) {
        int v = (t >= d) ? sd[t - d] : 0;
        __syncthreads();
        sd[t] += v;
        __syncthreads();
    }
    if (i < N) {
        int excl = g_bsumex[blockIdx.x] + sd[t] - c;
        g_off[i] = excl;
        g_cursor[i] = excl;
    }
}

__global__ void scatter_kernel(const int* __restrict__ edge, int E) {
    int i = blockIdx.x * blockDim.x + threadIdx.x;
    if (i >= E) return;
    int src = edge[i];
    int dst = edge[E + i];
    int pos = atomicAdd(&g_cursor[src], 1);
    g_csr_dst[pos] = dst;
}

// ---------------------------------------------------------------------------
// Fused aggregation: one 64-thread block per node, fp16 gathers.
// Thread t handles cols [t*4, t*4+4) — one uint2 (4 halfs) per row.
// ---------------------------------------------------------------------------
__device__ __forceinline__ float att(float s_src, int dst) {
    float logit = s_src + g_t[dst];
    float l = logit > 0.f ? logit : ALPHA * logit;
    return expf(-l);
}

__global__ void agg_kernel(float* __restrict__ out, int N) {
    int node = blockIdx.x;
    int f2 = threadIdx.x;                    // 0..63
    int beg = g_off[node];
    int deg = g_count[node];
    float s_src = g_s[node];

    const uint2* hp = reinterpret_cast<const uint2*>(g_hf16);
    float4 acc = make_float4(0.f, 0.f, 0.f, 0.f);
    float rowsum = 0.f;

    int j = 0;
    for (; j + 4 <= deg; j += 4) {
        int d0 = g_csr_dst[beg + j + 0];
        int d1 = g_csr_dst[beg + j + 1];
        int d2 = g_csr_dst[beg + j + 2];
        int d3 = g_csr_dst[beg + j + 3];
        float e0 = att(s_src, d0);
        float e1 = att(s_src, d1);
        float e2 = att(s_src, d2);
        float e3 = att(s_src, d3);
        uint2 u0 = hp[(size_t)d0 * 64 + f2];
        uint2 u1 = hp[(size_t)d1 * 64 + f2];
        uint2 u2 = hp[(size_t)d2 * 64 + f2];
        uint2 u3 = hp[(size_t)d3 * 64 + f2];
        rowsum += (e0 + e1) + (e2 + e3);
        float2 a0 = __half22float2(*reinterpret_cast<__half2*>(&u0.x));
        float2 b0 = __half22float2(*reinterpret_cast<__half2*>(&u0.y));
        float2 a1 = __half22float2(*reinterpret_cast<__half2*>(&u1.x));
        float2 b1 = __half22float2(*reinterpret_cast<__half2*>(&u1.y));
        float2 a2 = __half22float2(*reinterpret_cast<__half2*>(&u2.x));
        float2 b2 = __half22float2(*reinterpret_cast<__half2*>(&u2.y));
        float2 a3 = __half22float2(*reinterpret_cast<__half2*>(&u3.x));
        float2 b3 = __half22float2(*reinterpret_cast<__half2*>(&u3.y));
        acc.x += e0 * a0.x + e1 * a1.x + e2 * a2.x + e3 * a3.x;
        acc.y += e0 * a0.y + e1 * a1.y + e2 * a2.y + e3 * a3.y;
        acc.z += e0 * b0.x + e1 * b1.x + e2 * b2.x + e3 * b3.x;
        acc.w += e0 * b0.y + e1 * b1.y + e2 * b2.y + e3 * b3.y;
    }
    for (; j < deg; j++) {
        int d = g_csr_dst[beg + j];
        float e = att(s_src, d);
        uint2 u = hp[(size_t)d * 64 + f2];
        float2 p0 = __half22float2(*reinterpret_cast<__half2*>(&u.x));
        float2 p1 = __half22float2(*reinterpret_cast<__half2*>(&u.y));
        rowsum += e;
        acc.x += e * p0.x;
        acc.y += e * p0.y;
        acc.z += e * p1.x;
        acc.w += e * p1.y;
    }

    float inv = 1.0f / rowsum;
    float4 v;
    v.x = fmaxf(acc.x * inv, 0.f);
    v.y = fmaxf(acc.y * inv, 0.f);
    v.z = fmaxf(acc.z * inv, 0.f);
    v.w = fmaxf(acc.w * inv, 0.f);
    reinterpret_cast<float4*>(&out[(size_t)node * F])[f2] = v;
}

// ---------------------------------------------------------------------------
extern "C" void kernel_launch(void* const* d_in, const int* in_sizes, int n_in,
                              void* d_out, int out_size) {
    const float* x    = (const float*)d_in[0];
    const int*   edge = (const int*)d_in[1];
    const float* W    = (const float*)d_in[2];
    const float* a    = (const float*)d_in[3];
    float* out = (float*)d_out;

    int N = in_sizes[0] / F;
    int E = in_sizes[1] / 2;
    int nb = (N + SCAN_B - 1) / SCAN_B;

    // Lazy one-time setup (first call is the uncaptured correctness run)
    static cudaStream_t s2 = nullptr;
    static cudaEvent_t ev_fork = nullptr, ev_join = nullptr;
    if (!s2) {
        cudaStreamCreateWithFlags(&s2, cudaStreamNonBlocking);
        cudaEventCreateWithFlags(&ev_fork, cudaEventDisableTiming);
        cudaEventCreateWithFlags(&ev_join, cudaEventDisableTiming);
        cudaFuncSetAttribute(gemm_mma_kernel, cudaFuncAttributeMaxDynamicSharedMemorySize,
                             SM_GEMM_TOTAL);
    }

    void* p_count;
    cudaGetSymbolAddress(&p_count, g_count);

    // Fork: CSR build on s2, GEMM chain on stream 0 — independent until agg.
    cudaEventRecord(ev_fork, 0);
    cudaStreamWaitEvent(s2, ev_fork, 0);

    // --- stream s2: CSR build ---
    cudaMemsetAsync(p_count, 0, (size_t)N * sizeof(int), s2);
    hist_kernel<<<(E + 255) / 256, 256, 0, s2>>>(edge, E);
    bsum_kernel<<<nb, SCAN_B, 0, s2>>>(N);
    scan_top_kernel<<<1, SCAN_B, 0, s2>>>(nb);
    offsets_kernel<<<nb, SCAN_B, 0, s2>>>(N);
    scatter_kernel<<<(E + 255) / 256, 256, 0, s2>>>(edge, E);
    cudaEventRecord(ev_join, s2);

    // --- stream 0: GEMM chain ---
    convert_w_kernel<<<(F * F + 255) / 256, 256>>>(W);
    gemm_mma_kernel<<<(N + GBM - 1) / GBM, 256, SM_GEMM_TOTAL>>>(x, a, N);

    // Join, then fused aggregation
    cudaStreamWaitEvent(0, ev_join, 0);
    agg_kernel<<<N, 64>>>(out, N);
}

// round 9
// speedup vs baseline: 2.8282x; 1.1355x over previous
#include <cuda_runtime.h>
#include <cuda_bf16.h>
#include <cuda_fp16.h>
#include <cstdint>

#define NMAX 50000
#define EMAX 850000
#define F 256
#define ALPHA 0.2f
#define SCAN_B 256

// ---------------------------------------------------------------------------
// Scratch (__device__ globals — allocation-free rule)
// ---------------------------------------------------------------------------
__device__ __half g_hf16[NMAX * F];        // h = x @ W (fp16, gather payload)
__device__ float g_s[NMAX];                // h @ a[:F]
__device__ float g_t[NMAX];                // h @ a[F:]
__device__ __nv_bfloat16 g_wthi[F * F];    // W^T bf16 split ([n][k] K-major)
__device__ __nv_bfloat16 g_wtlo[F * F];
__device__ int g_count[NMAX];
__device__ int g_off[NMAX];
__device__ int g_cursor[NMAX];
__device__ int g_csr_dst[EMAX];
__device__ int g_bsum[SCAN_B];
__device__ int g_bsumex[SCAN_B];

// ---------------------------------------------------------------------------
// W transpose + bf16 split (tiny: 256KB)
// ---------------------------------------------------------------------------
__global__ void convert_w_kernel(const float* __restrict__ W) {
    int i = blockIdx.x * blockDim.x + threadIdx.x;  // i = n*256 + k
    if (i >= F * F) return;
    int n = i >> 8, k = i & 255;
    float v = W[k * F + n];
    __nv_bfloat16 h = __float2bfloat16(v);
    g_wthi[i] = h;
    g_wtlo[i] = __float2bfloat16(v - __bfloat162float(h));
}

// ---------------------------------------------------------------------------
// mma.sync bf16 GEMM: h = x @ W (3-product split), fused s/t epilogue.
// CTA: 64(M) x 256(N), K chunks of 64. 256 threads = 8 warps (2 M x 4 N).
// ---------------------------------------------------------------------------
__device__ __forceinline__ uint32_t smem_u32(const void* p) {
    uint32_t a;
    asm("{ .reg .u64 t; cvta.to.shared.u64 t, %1; cvt.u32.u64 %0, t; }" : "=r"(a) : "l"(p));
    return a;
}

__device__ __forceinline__ void ldsm_x4(uint32_t addr, uint32_t& r0, uint32_t& r1,
                                        uint32_t& r2, uint32_t& r3) {
    asm volatile("ldmatrix.sync.aligned.m8n8.x4.shared.b16 {%0,%1,%2,%3}, [%4];"
                 : "=r"(r0), "=r"(r1), "=r"(r2), "=r"(r3) : "r"(addr));
}

__device__ __forceinline__ void mma_bf16(float* d, const uint32_t* a, uint32_t b0, uint32_t b1) {
    asm volatile("mma.sync.aligned.m16n8k16.row.col.f32.bf16.bf16.f32 "
                 "{%0,%1,%2,%3}, {%4,%5,%6,%7}, {%8,%9}, {%0,%1,%2,%3};"
                 : "+f"(d[0]), "+f"(d[1]), "+f"(d[2]), "+f"(d[3])
                 : "r"(a[0]), "r"(a[1]), "r"(a[2]), "r"(a[3]), "r"(b0), "r"(b1));
}

#define GBM 64
#define ROWB 144
#define SM_SRED 0
#define SM_TRED 256
#define SM_A_HI 512
#define SM_A_LO (SM_A_HI + 9216)
#define SM_B_HI (SM_A_LO + 9216)
#define SM_B_LO (SM_B_HI + 36864)
#define SM_GEMM_TOTAL (SM_B_LO + 36864)   // 92672

__global__ void __launch_bounds__(256, 1) gemm_mma_kernel(const float* __restrict__ x,
                                                          const float* __restrict__ a, int M) {
    extern __shared__ char smem[];
    const uint32_t sbase = smem_u32(smem);
    const int tid = threadIdx.x;
    const int wid = tid >> 5;
    const int lane = tid & 31;
    const int wm = wid >> 2;
    const int wn = wid & 3;
    const int bm = blockIdx.x * GBM;

    float* s_red = reinterpret_cast<float*>(smem + SM_SRED);
    float* t_red = reinterpret_cast<float*>(smem + SM_TRED);
    if (tid < 64) { s_red[tid] = 0.f; t_red[tid] = 0.f; }

    float acc[2][8][4];
    #pragma unroll
    for (int mf = 0; mf < 2; mf++)
        #pragma unroll
        for (int nf = 0; nf < 8; nf++)
            #pragma unroll
            for (int j = 0; j < 4; j++) acc[mf][nf][j] = 0.f;

    const float4* x4 = reinterpret_cast<const float4*>(x);
    const uint4* whi4 = reinterpret_cast<const uint4*>(g_wthi);
    const uint4* wlo4 = reinterpret_cast<const uint4*>(g_wtlo);

    const int lr = lane & 15;
    const int lc = (lane >> 4) * 16;

    for (int c = 0; c < 4; c++) {
        #pragma unroll
        for (int i = tid; i < 1024; i += 256) {
            int row = i >> 4, q = i & 15;
            int grow = bm + row;
            float4 v = make_float4(0.f, 0.f, 0.f, 0.f);
            if (grow < M) v = x4[grow * 64 + c * 16 + q];
            __nv_bfloat162 h0, h1, l0, l1;
            h0.x = __float2bfloat16(v.x); h0.y = __float2bfloat16(v.y);
            h1.x = __float2bfloat16(v.z); h1.y = __float2bfloat16(v.w);
            l0.x = __float2bfloat16(v.x - __bfloat162float(h0.x));
            l0.y = __float2bfloat16(v.y - __bfloat162float(h0.y));
            l1.x = __float2bfloat16(v.z - __bfloat162float(h1.x));
            l1.y = __float2bfloat16(v.w - __bfloat162float(h1.y));
            uint32_t off = (uint32_t)(row * ROWB + q * 8);
            *reinterpret_cast<uint2*>(smem + SM_A_HI + off) =
                make_uint2(*reinterpret_cast<uint32_t*>(&h0), *reinterpret_cast<uint32_t*>(&h1));
            *reinterpret_cast<uint2*>(smem + SM_A_LO + off) =
                make_uint2(*reinterpret_cast<uint32_t*>(&l0), *reinterpret_cast<uint32_t*>(&l1));
        }
        #pragma unroll
        for (int i = tid; i < 2048; i += 256) {
            int n = i >> 3, q = i & 7;
            int gi = n * 32 + c * 8 + q;
            *reinterpret_cast<uint4*>(smem + SM_B_HI + n * ROWB + q * 16) = whi4[gi];
            *reinterpret_cast<uint4*>(smem + SM_B_LO + n * ROWB + q * 16) = wlo4[gi];
        }
        __syncthreads();

        #pragma unroll
        for (int ks = 0; ks < 4; ks++) {
            const uint32_t coff = (uint32_t)(ks * 32 + lc);
            uint32_t ah[2][4], al[2][4];
            #pragma unroll
            for (int mf = 0; mf < 2; mf++) {
                uint32_t arow = (uint32_t)(wm * 32 + mf * 16 + lr) * ROWB + coff;
                ldsm_x4(sbase + SM_A_HI + arow, ah[mf][0], ah[mf][1], ah[mf][2], ah[mf][3]);
                ldsm_x4(sbase + SM_A_LO + arow, al[mf][0], al[mf][1], al[mf][2], al[mf][3]);
            }
            #pragma unroll
            for (int nf2 = 0; nf2 < 4; nf2++) {
                uint32_t brow = (uint32_t)(wn * 64 + nf2 * 16 + lr) * ROWB + coff;
                uint32_t bh0, bh1, bh2, bh3, bl0, bl1, bl2, bl3;
                ldsm_x4(sbase + SM_B_HI + brow, bh0, bh1, bh2, bh3);
                ldsm_x4(sbase + SM_B_LO + brow, bl0, bl1, bl2, bl3);
                #pragma unroll
                for (int mf = 0; mf < 2; mf++) {
                    mma_bf16(acc[mf][nf2 * 2 + 0], ah[mf], bh0, bh2);
                    mma_bf16(acc[mf][nf2 * 2 + 0], ah[mf], bl0, bl2);
                    mma_bf16(acc[mf][nf2 * 2 + 0], al[mf], bh0, bh2);
                    mma_bf16(acc[mf][nf2 * 2 + 1], ah[mf], bh1, bh3);
                    mma_bf16(acc[mf][nf2 * 2 + 1], ah[mf], bl1, bl3);
                    mma_bf16(acc[mf][nf2 * 2 + 1], al[mf], bh1, bh3);
                }
            }
        }
        __syncthreads();
    }

    float av[16], atv[16];
    #pragma unroll
    for (int nf = 0; nf < 8; nf++)
        #pragma unroll
        for (int j = 0; j < 2; j++) {
            int col = wn * 64 + nf * 8 + (lane & 3) * 2 + j;
            av[nf * 2 + j] = a[col];
            atv[nf * 2 + j] = a[F + col];
        }

    #pragma unroll
    for (int mf = 0; mf < 2; mf++) {
        #pragma unroll
        for (int rg = 0; rg < 2; rg++) {
            int rloc = wm * 32 + mf * 16 + rg * 8 + (lane >> 2);
            int grow = bm + rloc;
            bool ok = grow < M;
            float sp = 0.f, tp = 0.f;
            #pragma unroll
            for (int nf = 0; nf < 8; nf++) {
                float d0 = acc[mf][nf][rg * 2 + 0];
                float d1 = acc[mf][nf][rg * 2 + 1];
                sp += d0 * av[nf * 2] + d1 * av[nf * 2 + 1];
                tp += d0 * atv[nf * 2] + d1 * atv[nf * 2 + 1];
                if (ok) {
                    int col = wn * 64 + nf * 8 + (lane & 3) * 2;
                    *reinterpret_cast<__half2*>(&g_hf16[(size_t)grow * F + col]) =
                        __floats2half2_rn(d0, d1);
                }
            }
            sp += __shfl_xor_sync(0xFFFFFFFF, sp, 1);
            sp += __shfl_xor_sync(0xFFFFFFFF, sp, 2);
            tp += __shfl_xor_sync(0xFFFFFFFF, tp, 1);
            tp += __shfl_xor_sync(0xFFFFFFFF, tp, 2);
            if ((lane & 3) == 0) {
                atomicAdd(&s_red[rloc], sp);
                atomicAdd(&t_red[rloc], tp);
            }
        }
    }
    __syncthreads();
    if (tid < 64 && bm + tid < M) {
        g_s[bm + tid] = s_red[tid];
        g_t[bm + tid] = t_red[tid];
    }
}

// ---------------------------------------------------------------------------
// CSR build: histogram -> block sums -> top scan -> offsets -> scatter
// ---------------------------------------------------------------------------
__global__ void hist_kernel(const int* __restrict__ edge, int E) {
    int i = blockIdx.x * blockDim.x + threadIdx.x;
    if (i < E) atomicAdd(&g_count[edge[i]], 1);
}

__global__ void bsum_kernel(int N) {
    __shared__ int sd[SCAN_B];
    int i = blockIdx.x * SCAN_B + threadIdx.x;
    sd[threadIdx.x] = (i < N) ? g_count[i] : 0;
    __syncthreads();
    #pragma unroll
    for (int d = SCAN_B / 2; d > 0; d >>= 1) {
        if (threadIdx.x < d) sd[threadIdx.x] += sd[threadIdx.x + d];
        __syncthreads();
    }
    if (threadIdx.x == 0) g_bsum[blockIdx.x] = sd[0];
}

__global__ void scan_top_kernel(int nb) {
    __shared__ int sd[SCAN_B];
    int t = threadIdx.x;
    sd[t] = (t < nb) ? g_bsum[t] : 0;
    __syncthreads();
    #pragma unroll
    for (int d = 1; d < SCAN_B; d <<= 1) {
        int v = (t >= d) ? sd[t - d] : 0;
        __syncthreads();
        sd[t] += v;
        __syncthreads();
    }
    int incl = sd[t];
    int own = (t < nb) ? g_bsum[t] : 0;
    if (t < nb) g_bsumex[t] = incl - own;
}

__global__ void offsets_kernel(int N) {
    __shared__ int sd[SCAN_B];
    int t = threadIdx.x;
    int i = blockIdx.x * SCAN_B + t;
    int c = (i < N) ? g_count[i] : 0;
    sd[t] = c;
    __syncthreads();
    #pragma unroll
    for (int d = 1; d < SCAN_B; d <<= 1) {
        int v = (t >= d) ? sd[t - d] : 0;
        __syncthreads();
        sd[t] += v;
        __syncthreads();
    }
    if (i < N) {
        int excl = g_bsumex[blockIdx.x] + sd[t] - c;
        g_off[i] = excl;
        g_cursor[i] = excl;
    }
}

__global__ void scatter_kernel(const int* __restrict__ edge, int E) {
    int i = blockIdx.x * blockDim.x + threadIdx.x;
    if (i >= E) return;
    int src = edge[i];
    int dst = edge[E + i];
    int pos = atomicAdd(&g_cursor[src], 1);
    g_csr_dst[pos] = dst;
}

// ---------------------------------------------------------------------------
// Fused aggregation v2: one WARP per node.
// Lane L owns h columns [L*8, L*8+8) (one uint4 of fp16 per gathered row).
// Edge batch of 32: lane j computes e_j once; (e, dst) broadcast via shfl.
// ---------------------------------------------------------------------------
__global__ void __launch_bounds__(256) agg_kernel(float* __restrict__ out, int N) {
    int warp_id = (blockIdx.x * blockDim.x + threadIdx.x) >> 5;
    int lane = threadIdx.x & 31;
    if (warp_id >= N) return;
    const int node = warp_id;
    const int beg = g_off[node];
    const int deg = g_count[node];
    const float s_src = g_s[node];

    const uint4* hp = reinterpret_cast<const uint4*>(g_hf16);  // 32 uint4 per row
    float acc[8];
    #pragma unroll
    for (int i = 0; i < 8; i++) acc[i] = 0.f;
    float rowsum = 0.f;

    for (int base = 0; base < deg; base += 32) {
        int j = base + lane;
        int d = 0;
        float e = 0.f;
        if (j < deg) {
            d = g_csr_dst[beg + j];
            float logit = s_src + g_t[d];
            float l = logit > 0.f ? logit : ALPHA * logit;
            e = __expf(-l);
            rowsum += e;
        }
        int cnt = min(32, deg - base);

        int k = 0;
        for (; k + 4 <= cnt; k += 4) {
            int d0 = __shfl_sync(0xFFFFFFFF, d, k + 0);
            int d1 = __shfl_sync(0xFFFFFFFF, d, k + 1);
            int d2 = __shfl_sync(0xFFFFFFFF, d, k + 2);
            int d3 = __shfl_sync(0xFFFFFFFF, d, k + 3);
            float e0 = __shfl_sync(0xFFFFFFFF, e, k + 0);
            float e1 = __shfl_sync(0xFFFFFFFF, e, k + 1);
            float e2 = __shfl_sync(0xFFFFFFFF, e, k + 2);
            float e3 = __shfl_sync(0xFFFFFFFF, e, k + 3);
            uint4 u0 = hp[(size_t)d0 * 32 + lane];
            uint4 u1 = hp[(size_t)d1 * 32 + lane];
            uint4 u2 = hp[(size_t)d2 * 32 + lane];
            uint4 u3 = hp[(size_t)d3 * 32 + lane];
            #pragma unroll
            for (int p = 0; p < 4; p++) {
                uint32_t w0 = (&u0.x)[p], w1 = (&u1.x)[p], w2 = (&u2.x)[p], w3 = (&u3.x)[p];
                float2 f0 = __half22float2(*reinterpret_cast<__half2*>(&w0));
                float2 f1 = __half22float2(*reinterpret_cast<__half2*>(&w1));
                float2 f2 = __half22float2(*reinterpret_cast<__half2*>(&w2));
                float2 f3 = __half22float2(*reinterpret_cast<__half2*>(&w3));
                acc[p * 2 + 0] += e0 * f0.x + e1 * f1.x + e2 * f2.x + e3 * f3.x;
                acc[p * 2 + 1] += e0 * f0.y + e1 * f1.y + e2 * f2.y + e3 * f3.y;
            }
        }
        for (; k < cnt; k++) {
            int dk = __shfl_sync(0xFFFFFFFF, d, k);
            float ek = __shfl_sync(0xFFFFFFFF, e, k);
            uint4 u = hp[(size_t)dk * 32 + lane];
            #pragma unroll
            for (int p = 0; p < 4; p++) {
                uint32_t w = (&u.x)[p];
                float2 f = __half22float2(*reinterpret_cast<__half2*>(&w));
                acc[p * 2 + 0] += ek * f.x;
                acc[p * 2 + 1] += ek * f.y;
            }
        }
    }

    #pragma unroll
    for (int off = 16; off > 0; off >>= 1)
        rowsum += __shfl_xor_sync(0xFFFFFFFF, rowsum, off);
    float inv = 1.0f / rowsum;

    float4* dst4 = reinterpret_cast<float4*>(&out[(size_t)node * F + lane * 8]);
    dst4[0] = make_float4(fmaxf(acc[0] * inv, 0.f), fmaxf(acc[1] * inv, 0.f),
                          fmaxf(acc[2] * inv, 0.f), fmaxf(acc[3] * inv, 0.f));
    dst4[1] = make_float4(fmaxf(acc[4] * inv, 0.f), fmaxf(acc[5] * inv, 0.f),
                          fmaxf(acc[6] * inv, 0.f), fmaxf(acc[7] * inv, 0.f));
}

// ---------------------------------------------------------------------------
extern "C" void kernel_launch(void* const* d_in, const int* in_sizes, int n_in,
                              void* d_out, int out_size) {
    const float* x    = (const float*)d_in[0];
    const int*   edge = (const int*)d_in[1];
    const float* W    = (const float*)d_in[2];
    const float* a    = (const float*)d_in[3];
    float* out = (float*)d_out;

    int N = in_sizes[0] / F;
    int E = in_sizes[1] / 2;
    int nb = (N + SCAN_B - 1) / SCAN_B;

    static cudaStream_t s2 = nullptr;
    static cudaEvent_t ev_fork = nullptr, ev_join = nullptr;
    if (!s2) {
        cudaStreamCreateWithFlags(&s2, cudaStreamNonBlocking);
        cudaEventCreateWithFlags(&ev_fork, cudaEventDisableTiming);
        cudaEventCreateWithFlags(&ev_join, cudaEventDisableTiming);
        cudaFuncSetAttribute(gemm_mma_kernel, cudaFuncAttributeMaxDynamicSharedMemorySize,
                             SM_GEMM_TOTAL);
    }

    void* p_count;
    cudaGetSymbolAddress(&p_count, g_count);

    cudaEventRecord(ev_fork, 0);
    cudaStreamWaitEvent(s2, ev_fork, 0);

    // --- stream s2: CSR build ---
    cudaMemsetAsync(p_count, 0, (size_t)N * sizeof(int), s2);
    hist_kernel<<<(E + 255) / 256, 256, 0, s2>>>(edge, E);
    bsum_kernel<<<nb, SCAN_B, 0, s2>>>(N);
    scan_top_kernel<<<1, SCAN_B, 0, s2>>>(nb);
    offsets_kernel<<<nb, SCAN_B, 0, s2>>>(N);
    scatter_kernel<<<(E + 255) / 256, 256, 0, s2>>>(edge, E);
    cudaEventRecord(ev_join, s2);

    // --- stream 0: GEMM chain ---
    convert_w_kernel<<<(F * F + 255) / 256, 256>>>(W);
    gemm_mma_kernel<<<(N + GBM - 1) / GBM, 256, SM_GEMM_TOTAL>>>(x, a, N);

    // Join, then fused aggregation (one warp per node)
    cudaStreamWaitEvent(0, ev_join, 0);
    agg_kernel<<<(N * 32 + 255) / 256, 256>>>(out, N);
}

// round 10
// speedup vs baseline: 3.2072x; 1.1340x over previous
#include <cuda_runtime.h>
#include <cuda_bf16.h>
#include <cuda_fp16.h>
#include <cstdint>

#define NMAX 50000
#define EMAX 850000
#define F 256
#define ALPHA 0.2f
#define SCAN_B 256

// ---------------------------------------------------------------------------
// Scratch (__device__ globals — allocation-free rule)
// ---------------------------------------------------------------------------
__device__ __half g_hf16[NMAX * F];        // h = x @ W (fp16, gather payload)
__device__ float g_s[NMAX];                // h @ a[:F]
__device__ float g_t[NMAX];                // h @ a[F:]
__device__ __nv_bfloat16 g_wthi[F * F];    // W^T bf16 split ([n][k] K-major)
__device__ __nv_bfloat16 g_wtlo[F * F];
__device__ int g_count[NMAX];
__device__ int g_off[NMAX];
__device__ int g_cursor[NMAX];
__device__ int g_csr_dst[EMAX];
__device__ int g_bsum[SCAN_B];
__device__ int g_bsumex[SCAN_B];

// ---------------------------------------------------------------------------
// W transpose + bf16 split, coalesced via 32x32 smem tile.
// grid (8,8), block (32,8).
// ---------------------------------------------------------------------------
__global__ void convert_w_kernel(const float* __restrict__ W) {
    __shared__ float tile[32][33];
    int k0 = blockIdx.x * 32;
    int n0 = blockIdx.y * 32;
    int tx = threadIdx.x, ty0 = threadIdx.y;
    #pragma unroll
    for (int dy = 0; dy < 32; dy += 8) {
        int ty = ty0 + dy;
        tile[ty][tx] = W[(size_t)(k0 + ty) * F + n0 + tx];   // coalesced read
    }
    __syncthreads();
    #pragma unroll
    for (int dy = 0; dy < 32; dy += 8) {
        int ty = ty0 + dy;                 // local n
        float v = tile[tx][ty];            // W[k0+tx][n0+ty] -> transposed
        __nv_bfloat16 h = __float2bfloat16(v);
        size_t oi = (size_t)(n0 + ty) * F + k0 + tx;
        g_wthi[oi] = h;
        g_wtlo[oi] = __float2bfloat16(v - __bfloat162float(h));
    }
}

// ---------------------------------------------------------------------------
// mma.sync bf16 GEMM: h = x @ W (3-product split), fused s/t epilogue.
// CTA: 128(M) x 256(N), K chunks of 64. 512 threads = 16 warps (4 M x 4 N).
// Warp tile 32x64, m16n8k16 fp32 accum.
// ---------------------------------------------------------------------------
__device__ __forceinline__ uint32_t smem_u32(const void* p) {
    uint32_t a;
    asm("{ .reg .u64 t; cvta.to.shared.u64 t, %1; cvt.u32.u64 %0, t; }" : "=r"(a) : "l"(p));
    return a;
}

__device__ __forceinline__ void ldsm_x4(uint32_t addr, uint32_t& r0, uint32_t& r1,
                                        uint32_t& r2, uint32_t& r3) {
    asm volatile("ldmatrix.sync.aligned.m8n8.x4.shared.b16 {%0,%1,%2,%3}, [%4];"
                 : "=r"(r0), "=r"(r1), "=r"(r2), "=r"(r3) : "r"(addr));
}

__device__ __forceinline__ void mma_bf16(float* d, const uint32_t* a, uint32_t b0, uint32_t b1) {
    asm volatile("mma.sync.aligned.m16n8k16.row.col.f32.bf16.bf16.f32 "
                 "{%0,%1,%2,%3}, {%4,%5,%6,%7}, {%8,%9}, {%0,%1,%2,%3};"
                 : "+f"(d[0]), "+f"(d[1]), "+f"(d[2]), "+f"(d[3])
                 : "r"(a[0]), "r"(a[1]), "r"(a[2]), "r"(a[3]), "r"(b0), "r"(b1));
}

#define GBM 128
#define GTHR 512
#define ROWB 144
#define SM_SRED 0                         // 128 floats
#define SM_TRED 512                       // 128 floats
#define SM_A_HI 1024                      // 128*144 = 18432
#define SM_A_LO (SM_A_HI + 18432)
#define SM_B_HI (SM_A_LO + 18432)         // 256*144 = 36864
#define SM_B_LO (SM_B_HI + 36864)
#define SM_GEMM_TOTAL (SM_B_LO + 36864)   // 111616

__global__ void __launch_bounds__(GTHR, 1) gemm_mma_kernel(const float* __restrict__ x,
                                                           const float* __restrict__ a, int M) {
    extern __shared__ char smem[];
    const uint32_t sbase = smem_u32(smem);
    const int tid = threadIdx.x;
    const int wid = tid >> 5;
    const int lane = tid & 31;
    const int wm = wid >> 2;          // 0..3 (32 rows each)
    const int wn = wid & 3;           // 0..3 (64 cols each)
    const int bm = blockIdx.x * GBM;

    float* s_red = reinterpret_cast<float*>(smem + SM_SRED);
    float* t_red = reinterpret_cast<float*>(smem + SM_TRED);
    if (tid < 128) { s_red[tid] = 0.f; t_red[tid] = 0.f; }

    float acc[2][8][4];
    #pragma unroll
    for (int mf = 0; mf < 2; mf++)
        #pragma unroll
        for (int nf = 0; nf < 8; nf++)
            #pragma unroll
            for (int j = 0; j < 4; j++) acc[mf][nf][j] = 0.f;

    const float4* x4 = reinterpret_cast<const float4*>(x);
    const uint4* whi4 = reinterpret_cast<const uint4*>(g_wthi);
    const uint4* wlo4 = reinterpret_cast<const uint4*>(g_wtlo);

    const int lr = lane & 15;
    const int lc = (lane >> 4) * 16;

    for (int c = 0; c < 4; c++) {
        // stage A: 128 rows x 64 fp32, split hi/lo in regs. 2048 float4 / 512thr.
        #pragma unroll
        for (int i = tid; i < 2048; i += GTHR) {
            int row = i >> 4, q = i & 15;
            int grow = bm + row;
            float4 v = make_float4(0.f, 0.f, 0.f, 0.f);
            if (grow < M) v = x4[grow * 64 + c * 16 + q];
            __nv_bfloat162 h0, h1, l0, l1;
            h0.x = __float2bfloat16(v.x); h0.y = __float2bfloat16(v.y);
            h1.x = __float2bfloat16(v.z); h1.y = __float2bfloat16(v.w);
            l0.x = __float2bfloat16(v.x - __bfloat162float(h0.x));
            l0.y = __float2bfloat16(v.y - __bfloat162float(h0.y));
            l1.x = __float2bfloat16(v.z - __bfloat162float(h1.x));
            l1.y = __float2bfloat16(v.w - __bfloat162float(h1.y));
            uint32_t off = (uint32_t)(row * ROWB + q * 8);
            *reinterpret_cast<uint2*>(smem + SM_A_HI + off) =
                make_uint2(*reinterpret_cast<uint32_t*>(&h0), *reinterpret_cast<uint32_t*>(&h1));
            *reinterpret_cast<uint2*>(smem + SM_A_LO + off) =
                make_uint2(*reinterpret_cast<uint32_t*>(&l0), *reinterpret_cast<uint32_t*>(&l1));
        }
        // stage B: 256 n-rows x 64 bf16 K (hi+lo). 2048 uint4 / 512thr.
        #pragma unroll
        for (int i = tid; i < 2048; i += GTHR) {
            int n = i >> 3, q = i & 7;
            int gi = n * 32 + c * 8 + q;
            *reinterpret_cast<uint4*>(smem + SM_B_HI + n * ROWB + q * 16) = whi4[gi];
            *reinterpret_cast<uint4*>(smem + SM_B_LO + n * ROWB + q * 16) = wlo4[gi];
        }
        __syncthreads();

        #pragma unroll
        for (int ks = 0; ks < 4; ks++) {
            const uint32_t coff = (uint32_t)(ks * 32 + lc);
            uint32_t ah[2][4], al[2][4];
            #pragma unroll
            for (int mf = 0; mf < 2; mf++) {
                uint32_t arow = (uint32_t)(wm * 32 + mf * 16 + lr) * ROWB + coff;
                ldsm_x4(sbase + SM_A_HI + arow, ah[mf][0], ah[mf][1], ah[mf][2], ah[mf][3]);
                ldsm_x4(sbase + SM_A_LO + arow, al[mf][0], al[mf][1], al[mf][2], al[mf][3]);
            }
            #pragma unroll
            for (int nf2 = 0; nf2 < 4; nf2++) {
                uint32_t brow = (uint32_t)(wn * 64 + nf2 * 16 + lr) * ROWB + coff;
                uint32_t bh0, bh1, bh2, bh3, bl0, bl1, bl2, bl3;
                ldsm_x4(sbase + SM_B_HI + brow, bh0, bh1, bh2, bh3);
                ldsm_x4(sbase + SM_B_LO + brow, bl0, bl1, bl2, bl3);
                #pragma unroll
                for (int mf = 0; mf < 2; mf++) {
                    mma_bf16(acc[mf][nf2 * 2 + 0], ah[mf], bh0, bh2);
                    mma_bf16(acc[mf][nf2 * 2 + 0], ah[mf], bl0, bl2);
                    mma_bf16(acc[mf][nf2 * 2 + 0], al[mf], bh0, bh2);
                    mma_bf16(acc[mf][nf2 * 2 + 1], ah[mf], bh1, bh3);
                    mma_bf16(acc[mf][nf2 * 2 + 1], ah[mf], bl1, bl3);
                    mma_bf16(acc[mf][nf2 * 2 + 1], al[mf], bh1, bh3);
                }
            }
        }
        __syncthreads();
    }

    // ---- epilogue: store h (fp16) + fused s/t ----
    float av[16], atv[16];
    #pragma unroll
    for (int nf = 0; nf < 8; nf++)
        #pragma unroll
        for (int j = 0; j < 2; j++) {
            int col = wn * 64 + nf * 8 + (lane & 3) * 2 + j;
            av[nf * 2 + j] = a[col];
            atv[nf * 2 + j] = a[F + col];
        }

    #pragma unroll
    for (int mf = 0; mf < 2; mf++) {
        #pragma unroll
        for (int rg = 0; rg < 2; rg++) {
            int rloc = wm * 32 + mf * 16 + rg * 8 + (lane >> 2);
            int grow = bm + rloc;
            bool ok = grow < M;
            float sp = 0.f, tp = 0.f;
            #pragma unroll
            for (int nf = 0; nf < 8; nf++) {
                float d0 = acc[mf][nf][rg * 2 + 0];
                float d1 = acc[mf][nf][rg * 2 + 1];
                sp += d0 * av[nf * 2] + d1 * av[nf * 2 + 1];
                tp += d0 * atv[nf * 2] + d1 * atv[nf * 2 + 1];
                if (ok) {
                    int col = wn * 64 + nf * 8 + (lane & 3) * 2;
                    *reinterpret_cast<__half2*>(&g_hf16[(size_t)grow * F + col]) =
                        __floats2half2_rn(d0, d1);
                }
            }
            sp += __shfl_xor_sync(0xFFFFFFFF, sp, 1);
            sp += __shfl_xor_sync(0xFFFFFFFF, sp, 2);
            tp += __shfl_xor_sync(0xFFFFFFFF, tp, 1);
            tp += __shfl_xor_sync(0xFFFFFFFF, tp, 2);
            if ((lane & 3) == 0) {
                atomicAdd(&s_red[rloc], sp);
                atomicAdd(&t_red[rloc], tp);
            }
        }
    }
    __syncthreads();
    if (tid < 128 && bm + tid < M) {
        g_s[bm + tid] = s_red[tid];
        g_t[bm + tid] = t_red[tid];
    }
}

// ---------------------------------------------------------------------------
// CSR build: histogram -> block sums -> top scan -> offsets -> scatter
// ---------------------------------------------------------------------------
__global__ void hist_kernel(const int* __restrict__ edge, int E) {
    int i = blockIdx.x * blockDim.x + threadIdx.x;
    if (i < E) atomicAdd(&g_count[edge[i]], 1);
}

__global__ void bsum_kernel(int N) {
    __shared__ int sd[SCAN_B];
    int i = blockIdx.x * SCAN_B + threadIdx.x;
    sd[threadIdx.x] = (i < N) ? g_count[i] : 0;
    __syncthreads();
    #pragma unroll
    for (int d = SCAN_B / 2; d > 0; d >>= 1) {
        if (threadIdx.x < d) sd[threadIdx.x] += sd[threadIdx.x + d];
        __syncthreads();
    }
    if (threadIdx.x == 0) g_bsum[blockIdx.x] = sd[0];
}

__global__ void scan_top_kernel(int nb) {
    __shared__ int sd[SCAN_B];
    int t = threadIdx.x;
    sd[t] = (t < nb) ? g_bsum[t] : 0;
    __syncthreads();
    #pragma unroll
    for (int d = 1; d < SCAN_B; d <<= 1) {
        int v = (t >= d) ? sd[t - d] : 0;
        __syncthreads();
        sd[t] += v;
        __syncthreads();
    }
    int incl = sd[t];
    int own = (t < nb) ? g_bsum[t] : 0;
    if (t < nb) g_bsumex[t] = incl - own;
}

__global__ void offsets_kernel(int N) {
    __shared__ int sd[SCAN_B];
    int t = threadIdx.x;
    int i = blockIdx.x * SCAN_B + t;
    int c = (i < N) ? g_count[i] : 0;
    sd[t] = c;
    __syncthreads();
    #pragma unroll
    for (int d = 1; d < SCAN_B; d <<= 1) {
        int v = (t >= d) ? sd[t - d] : 0;
        __syncthreads();
        sd[t] += v;
        __syncthreads();
    }
    if (i < N) {
        int excl = g_bsumex[blockIdx.x] + sd[t] - c;
        g_off[i] = excl;
        g_cursor[i] = excl;
    }
}

__global__ void scatter_kernel(const int* __restrict__ edge, int E) {
    int i = blockIdx.x * blockDim.x + threadIdx.x;
    if (i >= E) return;
    int src = edge[i];
    int dst = edge[E + i];
    int pos = atomicAdd(&g_cursor[src], 1);
    g_csr_dst[pos] = dst;
}

// ---------------------------------------------------------------------------
// Fused aggregation: one WARP per node, batch-padded (e=0 for pad lanes).
// Lane L owns h columns [L*8, L*8+8) (one uint4 of fp16 per gathered row).
// ---------------------------------------------------------------------------
__global__ void __launch_bounds__(256) agg_kernel(float* __restrict__ out, int N) {
    int warp_id = (blockIdx.x * blockDim.x + threadIdx.x) >> 5;
    int lane = threadIdx.x & 31;
    if (warp_id >= N) return;
    const int node = warp_id;
    const int beg = g_off[node];
    const int deg = g_count[node];
    const float s_src = g_s[node];

    const uint4* hp = reinterpret_cast<const uint4*>(g_hf16);  // 32 uint4 per row
    float acc[8];
    #pragma unroll
    for (int i = 0; i < 8; i++) acc[i] = 0.f;
    float rowsum = 0.f;

    for (int base = 0; base < deg; base += 32) {
        int j = base + lane;
        int d = 0;
        float e = 0.f;
        if (j < deg) {
            d = g_csr_dst[beg + j];
            float logit = s_src + g_t[d];
            float l = logit > 0.f ? logit : ALPHA * logit;
            e = __expf(-l);
            rowsum += e;
        }
        int cnt = min(32, deg - base);
        int cnt_r = (cnt + 3) & ~3;        // pad to x4; pad lanes have e=0, d=0

        for (int k = 0; k < cnt_r; k += 4) {
            int d0 = __shfl_sync(0xFFFFFFFF, d, k + 0);
            int d1 = __shfl_sync(0xFFFFFFFF, d, k + 1);
            int d2 = __shfl_sync(0xFFFFFFFF, d, k + 2);
            int d3 = __shfl_sync(0xFFFFFFFF, d, k + 3);
            float e0 = __shfl_sync(0xFFFFFFFF, e, k + 0);
            float e1 = __shfl_sync(0xFFFFFFFF, e, k + 1);
            float e2 = __shfl_sync(0xFFFFFFFF, e, k + 2);
            float e3 = __shfl_sync(0xFFFFFFFF, e, k + 3);
            uint4 u0 = hp[(size_t)d0 * 32 + lane];
            uint4 u1 = hp[(size_t)d1 * 32 + lane];
            uint4 u2 = hp[(size_t)d2 * 32 + lane];
            uint4 u3 = hp[(size_t)d3 * 32 + lane];
            #pragma unroll
            for (int p = 0; p < 4; p++) {
                uint32_t w0 = (&u0.x)[p], w1 = (&u1.x)[p], w2 = (&u2.x)[p], w3 = (&u3.x)[p];
                float2 f0 = __half22float2(*reinterpret_cast<__half2*>(&w0));
                float2 f1 = __half22float2(*reinterpret_cast<__half2*>(&w1));
                float2 f2 = __half22float2(*reinterpret_cast<__half2*>(&w2));
                float2 f3 = __half22float2(*reinterpret_cast<__half2*>(&w3));
                acc[p * 2 + 0] += e0 * f0.x + e1 * f1.x + e2 * f2.x + e3 * f3.x;
                acc[p * 2 + 1] += e0 * f0.y + e1 * f1.y + e2 * f2.y + e3 * f3.y;
            }
        }
    }

    #pragma unroll
    for (int off = 16; off > 0; off >>= 1)
        rowsum += __shfl_xor_sync(0xFFFFFFFF, rowsum, off);
    float inv = 1.0f / rowsum;

    float4* dst4 = reinterpret_cast<float4*>(&out[(size_t)node * F + lane * 8]);
    dst4[0] = make_float4(fmaxf(acc[0] * inv, 0.f), fmaxf(acc[1] * inv, 0.f),
                          fmaxf(acc[2] * inv, 0.f), fmaxf(acc[3] * inv, 0.f));
    dst4[1] = make_float4(fmaxf(acc[4] * inv, 0.f), fmaxf(acc[5] * inv, 0.f),
                          fmaxf(acc[6] * inv, 0.f), fmaxf(acc[7] * inv, 0.f));
}

// ---------------------------------------------------------------------------
extern "C" void kernel_launch(void* const* d_in, const int* in_sizes, int n_in,
                              void* d_out, int out_size) {
    const float* x    = (const float*)d_in[0];
    const int*   edge = (const int*)d_in[1];
    const float* W    = (const float*)d_in[2];
    const float* a    = (const float*)d_in[3];
    float* out = (float*)d_out;

    int N = in_sizes[0] / F;
    int E = in_sizes[1] / 2;
    int nb = (N + SCAN_B - 1) / SCAN_B;

    static cudaStream_t s2 = nullptr;
    static cudaEvent_t ev_fork = nullptr, ev_join = nullptr;
    if (!s2) {
        cudaStreamCreateWithFlags(&s2, cudaStreamNonBlocking);
        cudaEventCreateWithFlags(&ev_fork, cudaEventDisableTiming);
        cudaEventCreateWithFlags(&ev_join, cudaEventDisableTiming);
        cudaFuncSetAttribute(gemm_mma_kernel, cudaFuncAttributeMaxDynamicSharedMemorySize,
                             SM_GEMM_TOTAL);
    }

    void* p_count;
    cudaGetSymbolAddress(&p_count, g_count);

    cudaEventRecord(ev_fork, 0);
    cudaStreamWaitEvent(s2, ev_fork, 0);

    // --- stream s2: CSR build ---
    cudaMemsetAsync(p_count, 0, (size_t)N * sizeof(int), s2);
    hist_kernel<<<(E + 255) / 256, 256, 0, s2>>>(edge, E);
    bsum_kernel<<<nb, SCAN_B, 0, s2>>>(N);
    scan_top_kernel<<<1, SCAN_B, 0, s2>>>(nb);
    offsets_kernel<<<nb, SCAN_B, 0, s2>>>(N);
    scatter_kernel<<<(E + 255) / 256, 256, 0, s2>>>(edge, E);
    cudaEventRecord(ev_join, s2);

    // --- stream 0: GEMM chain ---
    convert_w_kernel<<<dim3(8, 8), dim3(32, 8)>>>(W);
    gemm_mma_kernel<<<(N + GBM - 1) / GBM, GTHR, SM_GEMM_TOTAL>>>(x, a, N);

    // Join, then fused aggregation (one warp per node)
    cudaStreamWaitEvent(0, ev_join, 0);
    agg_kernel<<<(N * 32 + 255) / 256, 256>>>(out, N);
}